// round 15
// baseline (speedup 1.0000x reference)
#include <cuda_runtime.h>
#include <cuda_bf16.h>
#include <cuda_fp16.h>
#include <math.h>

// Problem constants
#define BATCH   8
#define SEQ     2048
#define HID     256
#define NHEADS  8
#define HDIM    32
#define ROWS    (BATCH * SEQ)        // 16384

#define KV_PITCH 40    // attention K/V smem pitch (halfwords)
#define GP 40          // GEMM A-tile pitch (halfwords): 80B rows, ldmatrix-clean
#define WP 136         // GEMM B-tile pitch (halfwords): 272B rows, trans-ldmatrix-clean

#define NTILES (SEQ / 64)            // 32 KV tiles
#define KV_STAGES 4
#define KV_STAGE_BYTES (64 * KV_PITCH * 2)   // 5120 bytes per stage

// ---------------------------------------------------------------------------
// helpers
// ---------------------------------------------------------------------------
__device__ __forceinline__ unsigned smem_u32(const void* p) {
    return (unsigned)__cvta_generic_to_shared(p);
}
__device__ __forceinline__ void ldm_x4(unsigned r[4], unsigned addr) {
    asm volatile("ldmatrix.sync.aligned.m8n8.x4.shared.b16 {%0,%1,%2,%3}, [%4];"
        : "=r"(r[0]), "=r"(r[1]), "=r"(r[2]), "=r"(r[3]) : "r"(addr));
}
__device__ __forceinline__ void ldm_x4_t(unsigned r[4], unsigned addr) {
    asm volatile("ldmatrix.sync.aligned.m8n8.x4.trans.shared.b16 {%0,%1,%2,%3}, [%4];"
        : "=r"(r[0]), "=r"(r[1]), "=r"(r[2]), "=r"(r[3]) : "r"(addr));
}
// fp16 mma (everything)
__device__ __forceinline__ void mma16816h(float c[4], const unsigned a[4],
                                          unsigned b0, unsigned b1) {
    asm volatile("mma.sync.aligned.m16n8k16.row.col.f32.f16.f16.f32 "
        "{%0,%1,%2,%3}, {%4,%5,%6,%7}, {%8,%9}, {%0,%1,%2,%3};"
        : "+f"(c[0]), "+f"(c[1]), "+f"(c[2]), "+f"(c[3])
        : "r"(a[0]), "r"(a[1]), "r"(a[2]), "r"(a[3]), "r"(b0), "r"(b1));
}
__device__ __forceinline__ unsigned pack_h2(float x, float y) {
    __half2 h = __floats2half2_rn(x, y);
    return *reinterpret_cast<unsigned*>(&h);
}
__device__ __forceinline__ float ex2f(float x) {
    float y;
    asm("ex2.approx.f32 %0, %1;" : "=f"(y) : "f"(x));
    return y;
}
__device__ __forceinline__ void cp_async16(unsigned smem_addr, const void* gptr) {
    asm volatile("cp.async.cg.shared.global [%0], [%1], 16;"
        :: "r"(smem_addr), "l"(gptr));
}
__device__ __forceinline__ void cp_commit() {
    asm volatile("cp.async.commit_group;");
}
__device__ __forceinline__ void cp_wait2() {
    asm volatile("cp.async.wait_group 2;");
}

// Scratch (static device arrays — no allocation)
__device__ float g_q[BATCH * NHEADS * SEQ * HDIM];          // fp32 Q
__device__ __half g_kh[BATCH * NHEADS * SEQ * HDIM];        // K (fp16)
__device__ __half g_vh[BATCH * NHEADS * SEQ * HDIM];        // V (fp16)
__device__ float g_ctx[ROWS * HID];                         // [b*s][h*HDIM+d]

// ---------------------------------------------------------------------------
// Plain-fp16 tensor-core GEMM core: C[128,128] tile = A[128,K] @ W[K,128].
// fp32 accumulate. 8 warps as 4(m) x 2(n); per-warp 32 rows x 64 cols.
// ---------------------------------------------------------------------------
struct GemmSmem {
    __half Xs[128][GP];
    __half Ws[32][WP];
};

template <int LDA, int LDW, int KDIM>
__device__ __forceinline__ void gemm_core(GemmSmem* sm,
                                          const float* __restrict__ A, int m0,
                                          const float* __restrict__ W, int n0,
                                          float acc[2][8][4]) {
    const int tid = threadIdx.x;
    const int w  = tid >> 5;
    const int l  = tid & 31;
    const int wm = w >> 1;
    const int wn = w & 1;

    const int arow = l & 15;
    const int acol = 8 * (l >> 4);
    const int brow = (l & 7) + 8 * ((l >> 3) & 1);
    const int bcol = 8 * ((l >> 4) & 1);
    const unsigned x_b = smem_u32(&sm->Xs[0][0]);
    const unsigned w_b = smem_u32(&sm->Ws[0][0]);

    const int xrow = tid >> 3, xc = tid & 7;     // + 32*p rows
    const int wrow = tid >> 5, wc = tid & 31;    // + 8*p rows
    float4 xreg[4], wreg[4];
    #pragma unroll
    for (int p = 0; p < 4; p++) {
        xreg[p] = *(const float4*)&A[(size_t)(m0 + xrow + 32 * p) * LDA + xc * 4];
        wreg[p] = *(const float4*)&W[(size_t)(wrow + 8 * p) * LDW + n0 + wc * 4];
    }

    for (int kt = 0; kt < KDIM; kt += 32) {
        #pragma unroll
        for (int p = 0; p < 4; p++) {
            *(uint2*)&sm->Xs[xrow + 32 * p][xc * 4] =
                make_uint2(pack_h2(xreg[p].x, xreg[p].y), pack_h2(xreg[p].z, xreg[p].w));
            *(uint2*)&sm->Ws[wrow + 8 * p][wc * 4] =
                make_uint2(pack_h2(wreg[p].x, wreg[p].y), pack_h2(wreg[p].z, wreg[p].w));
        }
        __syncthreads();

        if (kt + 32 < KDIM) {
            #pragma unroll
            for (int p = 0; p < 4; p++) {
                xreg[p] = *(const float4*)&A[(size_t)(m0 + xrow + 32 * p) * LDA + kt + 32 + xc * 4];
                wreg[p] = *(const float4*)&W[(size_t)(kt + 32 + wrow + 8 * p) * LDW + n0 + wc * 4];
            }
        }

        #pragma unroll
        for (int kc = 0; kc < 2; kc++) {
            unsigned ah[2][4];
            #pragma unroll
            for (int mt = 0; mt < 2; mt++) {
                unsigned off = (unsigned)((32 * wm + 16 * mt + arow) * GP + 16 * kc + acol) * 2u;
                ldm_x4(ah[mt], x_b + off);
            }
            unsigned bh[4][4];
            #pragma unroll
            for (int g = 0; g < 4; g++) {
                unsigned off = (unsigned)((16 * kc + brow) * WP + 64 * wn + 16 * g + bcol) * 2u;
                ldm_x4_t(bh[g], w_b + off);
            }
            #pragma unroll
            for (int mt = 0; mt < 2; mt++)
                #pragma unroll
                for (int g = 0; g < 4; g++)
                    #pragma unroll
                    for (int x = 0; x < 2; x++)
                        mma16816h(acc[mt][2 * g + x], ah[mt], bh[g][2 * x], bh[g][2 * x + 1]);
        }
        __syncthreads();
    }
}

// ---------------------------------------------------------------------------
// QKV projection: [16384,256] @ [256,768] + b.
// Q fp32; K and V plain fp16.
// ---------------------------------------------------------------------------
__global__ __launch_bounds__(256) void qkv_mma(const float* __restrict__ X,
                                               const float* __restrict__ W,
                                               const float* __restrict__ bias) {
    __shared__ GemmSmem sm;
    const int m0 = blockIdx.y * 128;
    const int n0 = blockIdx.x * 128;

    float acc[2][8][4] = {};
    gemm_core<HID, 768, HID>(&sm, X, m0, W, n0, acc);

    const int l  = threadIdx.x & 31;
    const int w  = threadIdx.x >> 5;
    const int wm = w >> 1;
    const int wn = w & 1;
    const int sel = n0 >> 8;                       // 0=q,1=k,2=v

    #pragma unroll
    for (int mt = 0; mt < 2; mt++) {
        int r = m0 + 32 * wm + 16 * mt + (l >> 2);
        #pragma unroll
        for (int n8t = 0; n8t < 8; n8t++) {
            int col = n0 + 64 * wn + 8 * n8t + 2 * (l & 3);
            float bx = bias[col], by = bias[col + 1];
            int rem = col & 255;
            int nh = rem >> 5, hd = rem & 31;
            #pragma unroll
            for (int i = 0; i < 2; i++) {
                int rr = r + 8 * i;
                int b = rr >> 11, s = rr & 2047;
                float vx = acc[mt][n8t][2 * i] + bx;
                float vy = acc[mt][n8t][2 * i + 1] + by;
                size_t idx = ((size_t)(b * NHEADS + nh) * SEQ + s) * HDIM + hd;
                if (sel == 0) {
                    *(float2*)&g_q[idx] = make_float2(vx, vy);
                } else if (sel == 1) {
                    *(unsigned*)&g_kh[idx] = pack_h2(vx, vy);
                } else {
                    *(unsigned*)&g_vh[idx] = pack_h2(vx, vy);
                }
            }
        }
    }
}

// ---------------------------------------------------------------------------
// Output projection: out[16384,256] = ctx @ Wout[256,256] + b_out
// ---------------------------------------------------------------------------
__global__ __launch_bounds__(256) void out_mma(const float* __restrict__ W,
                                               const float* __restrict__ bias,
                                               float* __restrict__ out) {
    __shared__ GemmSmem sm;
    const int m0 = blockIdx.y * 128;
    const int n0 = blockIdx.x * 128;

    float acc[2][8][4] = {};
    gemm_core<HID, HID, HID>(&sm, g_ctx, m0, W, n0, acc);

    const int l  = threadIdx.x & 31;
    const int w  = threadIdx.x >> 5;
    const int wm = w >> 1;
    const int wn = w & 1;

    #pragma unroll
    for (int mt = 0; mt < 2; mt++) {
        int r = m0 + 32 * wm + 16 * mt + (l >> 2);
        #pragma unroll
        for (int n8t = 0; n8t < 8; n8t++) {
            int col = n0 + 64 * wn + 8 * n8t + 2 * (l & 3);
            float bx = bias[col], by = bias[col + 1];
            #pragma unroll
            for (int i = 0; i < 2; i++) {
                float2 v = make_float2(acc[mt][n8t][2 * i] + bx,
                                       acc[mt][n8t][2 * i + 1] + by);
                *(float2*)&out[(size_t)(r + 8 * i) * HID + col] = v;
            }
        }
    }
}

// ---------------------------------------------------------------------------
// Flash attention, plain fp16 mma (fp32 accumulate). 512 threads = 16 warps,
// each owning 32 q-rows (512-q-row block tile): 4 warps/SMSP for latency
// hiding without any register cap. cp.async 4-stage K/V pipeline; threads
// 0-255 copy K, 256-511 copy V (uniform commit counts across all threads).
// ---------------------------------------------------------------------------
__global__ __launch_bounds__(512) void attn_mma() {
    __shared__ __align__(16) __half Ks[KV_STAGES][64][KV_PITCH];
    __shared__ __align__(16) __half Vs[KV_STAGES][64][KV_PITCH];

    const int tid = threadIdx.x;
    const int w  = tid >> 5;             // 0..15
    const int l  = tid & 31;
    const int bh = blockIdx.y;
    const int b  = bh >> 3;
    const int h  = bh & 7;
    const int q0 = blockIdx.x * 512;
    // scale * log2(e): scores in log2 domain, exp = ex2
    const float scale2 = 0.1767766952966369f * 1.4426950408889634f;

    const size_t base = (size_t)(b * NHEADS + h) * SEQ * HDIM;
    const float* qp = g_q + base;
    const __half* khp = g_kh + base;
    const __half* vhp = g_vh + base;

    // Q fragments (plain fp16, scale folded), held for the whole kernel
    unsigned qh[2][2][4];
    const int qrow = q0 + w * 32 + (l >> 2);
    const int qcol = 2 * (l & 3);
    #pragma unroll
    for (int mt = 0; mt < 2; mt++)
        #pragma unroll
        for (int kc = 0; kc < 2; kc++)
            #pragma unroll
            for (int i = 0; i < 4; i++) {
                int r = qrow + 16 * mt + 8 * (i & 1);
                int c = qcol + 16 * kc + 8 * (i >> 1);
                float2 qv = *(const float2*)&qp[(size_t)r * HDIM + c];
                qh[mt][kc][i] = pack_h2(qv.x * scale2, qv.y * scale2);
            }

    float o[2][4][4] = {};
    float lsum[2][2] = {};

    const int krow_off = ((l >> 4) & 1) * 8 + (l & 7);
    const int kcol_off = ((l >> 3) & 1) * 8;
    const int vrow_off = ((l >> 3) & 1) * 8 + (l & 7);
    const int vcol_off = ((l >> 4) & 1) * 8;
    const unsigned kh_b = smem_u32(&Ks[0][0][0]);
    const unsigned vh_b = smem_u32(&Vs[0][0][0]);

    // cp.async mapping: tid<256 -> K, tid>=256 -> V. 64 rows x 4 x 16B chunks.
    const int cpid  = tid & 255;
    const int cprow = cpid >> 2;         // 0..63
    const int cpc16 = cpid & 3;          // 0..3
    const bool is_k = (tid < 256);
    const unsigned cp_dst0 = (is_k ? kh_b : vh_b)
        + (unsigned)(cprow * (KV_PITCH * 2) + cpc16 * 16);
    const __half* cp_src = is_k ? khp : vhp;

    // prologue: issue tiles 0 and 1
    #pragma unroll
    for (int t = 0; t < 2; t++) {
        size_t goff = (size_t)(t * 64 + cprow) * HDIM + cpc16 * 8;
        cp_async16(cp_dst0 + t * KV_STAGE_BYTES, cp_src + goff);
        cp_commit();
    }

    for (int t = 0; t < NTILES; t++) {
        const unsigned stoff = (unsigned)((t & 3) * KV_STAGE_BYTES);

        // issue tile t+2 (or an empty group to keep counts uniform)
        if (t + 2 < NTILES) {
            size_t goff = (size_t)((t + 2) * 64 + cprow) * HDIM + cpc16 * 8;
            cp_async16(cp_dst0 + ((t + 2) & 3) * KV_STAGE_BYTES, cp_src + goff);
        }
        cp_commit();
        cp_wait2();          // tile t's group complete (2 newer groups pending)
        __syncthreads();     // make all threads' copies visible

        #pragma unroll
        for (int c = 0; c < 4; c++) {
            unsigned bk[2][4];
            {
                int kr = (16 * c + krow_off) * KV_PITCH;
                ldm_x4(bk[0], kh_b + stoff + (unsigned)(kr + kcol_off) * 2u);
                ldm_x4(bk[1], kh_b + stoff + (unsigned)(kr + 16 + kcol_off) * 2u);
            }

            float s[2][2][4] = {};
            #pragma unroll
            for (int mt = 0; mt < 2; mt++)
                #pragma unroll
                for (int ntl = 0; ntl < 2; ntl++) {
                    float* sc = s[mt][ntl];
                    mma16816h(sc, qh[mt][0], bk[0][2 * ntl], bk[0][2 * ntl + 1]);
                    mma16816h(sc, qh[mt][1], bk[1][2 * ntl], bk[1][2 * ntl + 1]);
                }

            // exp -> plain fp16 P fragments; fp32 row-sum partials
            unsigned pa[2][4];
            #pragma unroll
            for (int mt = 0; mt < 2; mt++) {
                float e00 = ex2f(s[mt][0][0]), e01 = ex2f(s[mt][0][1]);
                float e02 = ex2f(s[mt][0][2]), e03 = ex2f(s[mt][0][3]);
                float e10 = ex2f(s[mt][1][0]), e11 = ex2f(s[mt][1][1]);
                float e12 = ex2f(s[mt][1][2]), e13 = ex2f(s[mt][1][3]);
                lsum[mt][0] += (e00 + e01) + (e10 + e11);
                lsum[mt][1] += (e02 + e03) + (e12 + e13);
                pa[mt][0] = pack_h2(e00, e01);
                pa[mt][1] = pack_h2(e02, e03);
                pa[mt][2] = pack_h2(e10, e11);
                pa[mt][3] = pack_h2(e12, e13);
            }

            unsigned bv[2][4];
            {
                int vr = (16 * c + vrow_off) * KV_PITCH;
                ldm_x4_t(bv[0], vh_b + stoff + (unsigned)(vr + vcol_off) * 2u);
                ldm_x4_t(bv[1], vh_b + stoff + (unsigned)(vr + 16 + vcol_off) * 2u);
            }

            #pragma unroll
            for (int mt = 0; mt < 2; mt++)
                #pragma unroll
                for (int nt = 0; nt < 4; nt++) {
                    int p = nt >> 1, x = nt & 1;
                    mma16816h(o[mt][nt], pa[mt], bv[p][2 * x], bv[p][2 * x + 1]);
                }
        }
    }

    float inv[2][2];
    #pragma unroll
    for (int mt = 0; mt < 2; mt++)
        #pragma unroll
        for (int j = 0; j < 2; j++) {
            float v = lsum[mt][j];
            v += __shfl_xor_sync(0xffffffffu, v, 1);
            v += __shfl_xor_sync(0xffffffffu, v, 2);
            inv[mt][j] = 1.0f / v;
        }

    #pragma unroll
    for (int mt = 0; mt < 2; mt++) {
        int r0 = q0 + w * 32 + 16 * mt + (l >> 2);
        #pragma unroll
        for (int nt = 0; nt < 4; nt++) {
            int col = h * HDIM + 8 * nt + 2 * (l & 3);
            float2 lo = make_float2(o[mt][nt][0] * inv[mt][0], o[mt][nt][1] * inv[mt][0]);
            float2 hi = make_float2(o[mt][nt][2] * inv[mt][1], o[mt][nt][3] * inv[mt][1]);
            *(float2*)&g_ctx[((size_t)b * SEQ + r0) * HID + col] = lo;
            *(float2*)&g_ctx[((size_t)b * SEQ + r0 + 8) * HID + col] = hi;
        }
    }
}

// ---------------------------------------------------------------------------
extern "C" void kernel_launch(void* const* d_in, const int* in_sizes, int n_in,
                              void* d_out, int out_size) {
    const float* x     = (const float*)d_in[0];
    const float* w_qkv = (const float*)d_in[1];
    const float* b_qkv = (const float*)d_in[2];
    const float* w_out = (const float*)d_in[3];
    const float* b_out = (const float*)d_in[4];
    float* out = (float*)d_out;

    qkv_mma<<<dim3(6, ROWS / 128), 256>>>(x, w_qkv, b_qkv);
    attn_mma<<<dim3(SEQ / 512, BATCH * NHEADS), 512>>>();
    out_mma<<<dim3(2, ROWS / 128), 256>>>(w_out, b_out, out);
}

// round 16
// speedup vs baseline: 1.0636x; 1.0636x over previous
#include <cuda_runtime.h>
#include <cuda_bf16.h>
#include <cuda_fp16.h>
#include <math.h>

// Problem constants
#define BATCH   8
#define SEQ     2048
#define HID     256
#define NHEADS  8
#define HDIM    32
#define ROWS    (BATCH * SEQ)        // 16384

#define KV_PITCH 40    // attention K/V smem pitch (halfwords)
#define GP 40          // GEMM A-tile pitch (halfwords): 80B rows, ldmatrix-clean
#define WP 136         // GEMM B-tile pitch (halfwords): 272B rows, trans-ldmatrix-clean

#define NTILES (SEQ / 64)            // 32 KV tiles
#define KV_STAGES 4
#define KV_STAGE_BYTES (64 * KV_PITCH * 2)   // 5120 bytes per stage

#define XS_STAGE_BYTES (128 * GP * 2)        // 10240
#define WS_STAGE_BYTES (32 * WP * 2)         // 8704

// ---------------------------------------------------------------------------
// helpers
// ---------------------------------------------------------------------------
__device__ __forceinline__ unsigned smem_u32(const void* p) {
    return (unsigned)__cvta_generic_to_shared(p);
}
__device__ __forceinline__ void ldm_x4(unsigned r[4], unsigned addr) {
    asm volatile("ldmatrix.sync.aligned.m8n8.x4.shared.b16 {%0,%1,%2,%3}, [%4];"
        : "=r"(r[0]), "=r"(r[1]), "=r"(r[2]), "=r"(r[3]) : "r"(addr));
}
__device__ __forceinline__ void ldm_x4_t(unsigned r[4], unsigned addr) {
    asm volatile("ldmatrix.sync.aligned.m8n8.x4.trans.shared.b16 {%0,%1,%2,%3}, [%4];"
        : "=r"(r[0]), "=r"(r[1]), "=r"(r[2]), "=r"(r[3]) : "r"(addr));
}
// fp16 mma (everything)
__device__ __forceinline__ void mma16816h(float c[4], const unsigned a[4],
                                          unsigned b0, unsigned b1) {
    asm volatile("mma.sync.aligned.m16n8k16.row.col.f32.f16.f16.f32 "
        "{%0,%1,%2,%3}, {%4,%5,%6,%7}, {%8,%9}, {%0,%1,%2,%3};"
        : "+f"(c[0]), "+f"(c[1]), "+f"(c[2]), "+f"(c[3])
        : "r"(a[0]), "r"(a[1]), "r"(a[2]), "r"(a[3]), "r"(b0), "r"(b1));
}
__device__ __forceinline__ unsigned pack_h2(float x, float y) {
    __half2 h = __floats2half2_rn(x, y);
    return *reinterpret_cast<unsigned*>(&h);
}
__device__ __forceinline__ float ex2f(float x) {
    float y;
    asm("ex2.approx.f32 %0, %1;" : "=f"(y) : "f"(x));
    return y;
}
__device__ __forceinline__ void cp_async16(unsigned smem_addr, const void* gptr) {
    asm volatile("cp.async.cg.shared.global [%0], [%1], 16;"
        :: "r"(smem_addr), "l"(gptr));
}
__device__ __forceinline__ void cp_commit() {
    asm volatile("cp.async.commit_group;");
}
__device__ __forceinline__ void cp_wait1() {
    asm volatile("cp.async.wait_group 1;");
}
__device__ __forceinline__ void cp_wait2() {
    asm volatile("cp.async.wait_group 2;");
}

// Scratch (static device arrays — no allocation)
__device__ __half g_xh[ROWS * HID];                         // X fp16
__device__ __half g_wqkvh[HID * 768];                       // Wqkv fp16
__device__ __half g_wouth[HID * HID];                       // Wout fp16
__device__ __half g_qh[BATCH * NHEADS * SEQ * HDIM];        // Q fp16 (scale2 folded)
__device__ __half g_kh[BATCH * NHEADS * SEQ * HDIM];        // K fp16
__device__ __half g_vh[BATCH * NHEADS * SEQ * HDIM];        // V fp16
__device__ __half g_ctxh[ROWS * HID];                       // ctx fp16

// ---------------------------------------------------------------------------
// Prep: convert fp32 inputs to fp16 (identical rounding to what the GEMM
// store phase previously did in SMEM — bit-identical results downstream).
// ---------------------------------------------------------------------------
#define NX4  (ROWS * HID / 4)        // 1048576
#define NW14 (HID * 768 / 4)         // 49152
#define NW24 (HID * HID / 4)         // 16384
#define NPREP (NX4 + NW14 + NW24)

__global__ __launch_bounds__(256) void prep_half(const float* __restrict__ x,
                                                 const float* __restrict__ wqkv,
                                                 const float* __restrict__ wout) {
    int i = blockIdx.x * blockDim.x + threadIdx.x;
    if (i >= NPREP) return;
    const float4* src;
    __half* dst;
    int j;
    if (i < NX4)              { src = (const float4*)x;    dst = g_xh;    j = i; }
    else if (i < NX4 + NW14)  { src = (const float4*)wqkv; dst = g_wqkvh; j = i - NX4; }
    else                      { src = (const float4*)wout; dst = g_wouth; j = i - NX4 - NW14; }
    float4 v = src[j];
    *(uint2*)&dst[j * 4] = make_uint2(pack_h2(v.x, v.y), pack_h2(v.z, v.w));
}

// ---------------------------------------------------------------------------
// fp16 cp.async GEMM core: C[128,128] tile = A[128,K] @ W[K,128], fp32 accum.
// 2-stage pipeline; the two per-iteration barriers order stage reuse.
// 8 warps as 4(m) x 2(n); per-warp 32 rows x 64 cols.
// ---------------------------------------------------------------------------
struct GemmSmemH {
    __half Xs[2][128][GP];
    __half Ws[2][32][WP];
};

template <int LDA, int LDW, int KDIM>
__device__ __forceinline__ void gemm_core_h(GemmSmemH* sm,
                                            const __half* __restrict__ A, int m0,
                                            const __half* __restrict__ W, int n0,
                                            float acc[2][8][4]) {
    const int tid = threadIdx.x;
    const int w  = tid >> 5;
    const int l  = tid & 31;
    const int wm = w >> 1;
    const int wn = w & 1;

    const int arow = l & 15;
    const int acol = 8 * (l >> 4);
    const int brow = (l & 7) + 8 * ((l >> 3) & 1);
    const int bcol = 8 * ((l >> 4) & 1);
    const unsigned x_b = smem_u32(&sm->Xs[0][0][0]);
    const unsigned w_b = smem_u32(&sm->Ws[0][0][0]);

    // cp.async chunk mapping (2 X-chunks + 2 W-chunks per thread per k-iter)
    // X tile 128x32 halfs: 4 x 16B chunks/row -> 512 chunks.
    // W tile 32x128 halfs: 16 x 16B chunks/row -> 512 chunks.
    const int NK = KDIM / 32;

    // prologue: issue k-iter 0 into stage 0
    #pragma unroll
    for (int p = 0; p < 2; p++) {
        int id = tid + p * 256;
        int xr = id >> 2, xc = id & 3;
        cp_async16(x_b + (unsigned)(xr * (GP * 2) + xc * 16),
                   A + (size_t)(m0 + xr) * LDA + xc * 8);
        int wr = id >> 4, wc = id & 15;
        cp_async16(w_b + (unsigned)(wr * (WP * 2) + wc * 16),
                   W + (size_t)wr * LDW + n0 + wc * 8);
    }
    cp_commit();

    for (int i = 0; i < NK; i++) {
        const int st = i & 1;
        // issue k-iter i+1 into the other stage
        if (i + 1 < NK) {
            const unsigned xoff = (unsigned)((st ^ 1) * XS_STAGE_BYTES);
            const unsigned woff = (unsigned)((st ^ 1) * WS_STAGE_BYTES);
            const int kt = (i + 1) * 32;
            #pragma unroll
            for (int p = 0; p < 2; p++) {
                int id = tid + p * 256;
                int xr = id >> 2, xc = id & 3;
                cp_async16(x_b + xoff + (unsigned)(xr * (GP * 2) + xc * 16),
                           A + (size_t)(m0 + xr) * LDA + kt + xc * 8);
                int wr = id >> 4, wc = id & 15;
                cp_async16(w_b + woff + (unsigned)(wr * (WP * 2) + wc * 16),
                           W + (size_t)(kt + wr) * LDW + n0 + wc * 8);
            }
        }
        cp_commit();
        cp_wait1();          // k-iter i's group complete (1 newer pending)
        __syncthreads();

        const unsigned xoff = (unsigned)(st * XS_STAGE_BYTES);
        const unsigned woff = (unsigned)(st * WS_STAGE_BYTES);
        #pragma unroll
        for (int kc = 0; kc < 2; kc++) {
            unsigned ah[2][4];
            #pragma unroll
            for (int mt = 0; mt < 2; mt++) {
                unsigned off = (unsigned)((32 * wm + 16 * mt + arow) * GP + 16 * kc + acol) * 2u;
                ldm_x4(ah[mt], x_b + xoff + off);
            }
            unsigned bh[4][4];
            #pragma unroll
            for (int g = 0; g < 4; g++) {
                unsigned off = (unsigned)((16 * kc + brow) * WP + 64 * wn + 16 * g + bcol) * 2u;
                ldm_x4_t(bh[g], w_b + woff + off);
            }
            #pragma unroll
            for (int mt = 0; mt < 2; mt++)
                #pragma unroll
                for (int g = 0; g < 4; g++)
                    #pragma unroll
                    for (int x = 0; x < 2; x++)
                        mma16816h(acc[mt][2 * g + x], ah[mt], bh[g][2 * x], bh[g][2 * x + 1]);
        }
        __syncthreads();     // orders stage reuse (rewritten at iter i+2)
    }
}

// ---------------------------------------------------------------------------
// QKV projection: Q fp16 (scale2 pre-folded), K and V fp16.
// ---------------------------------------------------------------------------
__global__ __launch_bounds__(256) void qkv_mma(const float* __restrict__ bias) {
    __shared__ GemmSmemH sm;
    const int m0 = blockIdx.y * 128;
    const int n0 = blockIdx.x * 128;

    float acc[2][8][4] = {};
    gemm_core_h<HID, 768, HID>(&sm, g_xh, m0, g_wqkvh, n0, acc);

    const int l  = threadIdx.x & 31;
    const int w  = threadIdx.x >> 5;
    const int wm = w >> 1;
    const int wn = w & 1;
    const int sel = n0 >> 8;                       // 0=q,1=k,2=v
    const float scale2 = 0.1767766952966369f * 1.4426950408889634f;

    #pragma unroll
    for (int mt = 0; mt < 2; mt++) {
        int r = m0 + 32 * wm + 16 * mt + (l >> 2);
        #pragma unroll
        for (int n8t = 0; n8t < 8; n8t++) {
            int col = n0 + 64 * wn + 8 * n8t + 2 * (l & 3);
            float bx = bias[col], by = bias[col + 1];
            int rem = col & 255;
            int nh = rem >> 5, hd = rem & 31;
            #pragma unroll
            for (int i = 0; i < 2; i++) {
                int rr = r + 8 * i;
                int b = rr >> 11, s = rr & 2047;
                float vx = acc[mt][n8t][2 * i] + bx;
                float vy = acc[mt][n8t][2 * i + 1] + by;
                size_t idx = ((size_t)(b * NHEADS + nh) * SEQ + s) * HDIM + hd;
                if (sel == 0) {
                    *(unsigned*)&g_qh[idx] = pack_h2(vx * scale2, vy * scale2);
                } else if (sel == 1) {
                    *(unsigned*)&g_kh[idx] = pack_h2(vx, vy);
                } else {
                    *(unsigned*)&g_vh[idx] = pack_h2(vx, vy);
                }
            }
        }
    }
}

// ---------------------------------------------------------------------------
// Output projection: out[16384,256] = ctx @ Wout[256,256] + b_out
// ---------------------------------------------------------------------------
__global__ __launch_bounds__(256) void out_mma(const float* __restrict__ bias,
                                               float* __restrict__ out) {
    __shared__ GemmSmemH sm;
    const int m0 = blockIdx.y * 128;
    const int n0 = blockIdx.x * 128;

    float acc[2][8][4] = {};
    gemm_core_h<HID, HID, HID>(&sm, g_ctxh, m0, g_wouth, n0, acc);

    const int l  = threadIdx.x & 31;
    const int w  = threadIdx.x >> 5;
    const int wm = w >> 1;
    const int wn = w & 1;

    #pragma unroll
    for (int mt = 0; mt < 2; mt++) {
        int r = m0 + 32 * wm + 16 * mt + (l >> 2);
        #pragma unroll
        for (int n8t = 0; n8t < 8; n8t++) {
            int col = n0 + 64 * wn + 8 * n8t + 2 * (l & 3);
            float bx = bias[col], by = bias[col + 1];
            #pragma unroll
            for (int i = 0; i < 2; i++) {
                float2 v = make_float2(acc[mt][n8t][2 * i] + bx,
                                       acc[mt][n8t][2 * i + 1] + by);
                *(float2*)&out[(size_t)(r + 8 * i) * HID + col] = v;
            }
        }
    }
}

// ---------------------------------------------------------------------------
// Flash attention, plain fp16 mma (fp32 accumulate). 256 threads (round-13
// config). cp.async 4-stage K/V pipeline. Q read directly as fp16 (scale
// pre-folded in qkv epilogue); ctx written as fp16 (rounding identical to
// the former out_mma pack).
// ---------------------------------------------------------------------------
__global__ __launch_bounds__(256) void attn_mma() {
    __shared__ __align__(16) __half Ks[KV_STAGES][64][KV_PITCH];
    __shared__ __align__(16) __half Vs[KV_STAGES][64][KV_PITCH];

    const int tid = threadIdx.x;
    const int w  = tid >> 5;
    const int l  = tid & 31;
    const int bh = blockIdx.y;
    const int b  = bh >> 3;
    const int h  = bh & 7;
    const int q0 = blockIdx.x * 256;

    const size_t base = (size_t)(b * NHEADS + h) * SEQ * HDIM;
    const __half* qp = g_qh + base;
    const __half* khp = g_kh + base;
    const __half* vhp = g_vh + base;

    // Q fragments: direct fp16 loads (scale2 already folded)
    unsigned qh[2][2][4];
    const int qrow = q0 + w * 32 + (l >> 2);
    const int qcol = 2 * (l & 3);
    #pragma unroll
    for (int mt = 0; mt < 2; mt++)
        #pragma unroll
        for (int kc = 0; kc < 2; kc++)
            #pragma unroll
            for (int i = 0; i < 4; i++) {
                int r = qrow + 16 * mt + 8 * (i & 1);
                int c = qcol + 16 * kc + 8 * (i >> 1);
                qh[mt][kc][i] = *(const unsigned*)&qp[(size_t)r * HDIM + c];
            }

    float o[2][4][4] = {};
    float lsum[2][2] = {};

    const int krow_off = ((l >> 4) & 1) * 8 + (l & 7);
    const int kcol_off = ((l >> 3) & 1) * 8;
    const int vrow_off = ((l >> 3) & 1) * 8 + (l & 7);
    const int vcol_off = ((l >> 4) & 1) * 8;
    const unsigned kh_b = smem_u32(&Ks[0][0][0]);
    const unsigned vh_b = smem_u32(&Vs[0][0][0]);

    // cp.async mapping: thread -> (row, 16B chunk). 64 rows x 4 chunks = 256.
    const int cprow = tid >> 2;          // 0..63
    const int cpc16 = tid & 3;           // 0..3 (16B = 8 halfs each)
    const unsigned k_dst0 = kh_b + (unsigned)(cprow * (KV_PITCH * 2) + cpc16 * 16);
    const unsigned v_dst0 = vh_b + (unsigned)(cprow * (KV_PITCH * 2) + cpc16 * 16);

    // prologue: issue tiles 0 and 1
    #pragma unroll
    for (int t = 0; t < 2; t++) {
        size_t goff = (size_t)(t * 64 + cprow) * HDIM + cpc16 * 8;
        cp_async16(k_dst0 + t * KV_STAGE_BYTES, khp + goff);
        cp_async16(v_dst0 + t * KV_STAGE_BYTES, vhp + goff);
        cp_commit();
    }

    for (int t = 0; t < NTILES; t++) {
        const unsigned stoff = (unsigned)((t & 3) * KV_STAGE_BYTES);

        // issue tile t+2 (or an empty group to keep counts uniform)
        if (t + 2 < NTILES) {
            size_t goff = (size_t)((t + 2) * 64 + cprow) * HDIM + cpc16 * 8;
            cp_async16(k_dst0 + ((t + 2) & 3) * KV_STAGE_BYTES, khp + goff);
            cp_async16(v_dst0 + ((t + 2) & 3) * KV_STAGE_BYTES, vhp + goff);
        }
        cp_commit();
        cp_wait2();          // tile t's group complete (2 newer groups pending)
        __syncthreads();     // make all threads' copies visible

        #pragma unroll
        for (int c = 0; c < 4; c++) {
            unsigned bk[2][4];
            {
                int kr = (16 * c + krow_off) * KV_PITCH;
                ldm_x4(bk[0], kh_b + stoff + (unsigned)(kr + kcol_off) * 2u);
                ldm_x4(bk[1], kh_b + stoff + (unsigned)(kr + 16 + kcol_off) * 2u);
            }

            float s[2][2][4] = {};
            #pragma unroll
            for (int mt = 0; mt < 2; mt++)
                #pragma unroll
                for (int ntl = 0; ntl < 2; ntl++) {
                    float* sc = s[mt][ntl];
                    mma16816h(sc, qh[mt][0], bk[0][2 * ntl], bk[0][2 * ntl + 1]);
                    mma16816h(sc, qh[mt][1], bk[1][2 * ntl], bk[1][2 * ntl + 1]);
                }

            // exp -> plain fp16 P fragments; fp32 row-sum partials
            unsigned pa[2][4];
            #pragma unroll
            for (int mt = 0; mt < 2; mt++) {
                float e00 = ex2f(s[mt][0][0]), e01 = ex2f(s[mt][0][1]);
                float e02 = ex2f(s[mt][0][2]), e03 = ex2f(s[mt][0][3]);
                float e10 = ex2f(s[mt][1][0]), e11 = ex2f(s[mt][1][1]);
                float e12 = ex2f(s[mt][1][2]), e13 = ex2f(s[mt][1][3]);
                lsum[mt][0] += (e00 + e01) + (e10 + e11);
                lsum[mt][1] += (e02 + e03) + (e12 + e13);
                pa[mt][0] = pack_h2(e00, e01);
                pa[mt][1] = pack_h2(e02, e03);
                pa[mt][2] = pack_h2(e10, e11);
                pa[mt][3] = pack_h2(e12, e13);
            }

            unsigned bv[2][4];
            {
                int vr = (16 * c + vrow_off) * KV_PITCH;
                ldm_x4_t(bv[0], vh_b + stoff + (unsigned)(vr + vcol_off) * 2u);
                ldm_x4_t(bv[1], vh_b + stoff + (unsigned)(vr + 16 + vcol_off) * 2u);
            }

            #pragma unroll
            for (int mt = 0; mt < 2; mt++)
                #pragma unroll
                for (int nt = 0; nt < 4; nt++) {
                    int p = nt >> 1, x = nt & 1;
                    mma16816h(o[mt][nt], pa[mt], bv[p][2 * x], bv[p][2 * x + 1]);
                }
        }
    }

    float inv[2][2];
    #pragma unroll
    for (int mt = 0; mt < 2; mt++)
        #pragma unroll
        for (int j = 0; j < 2; j++) {
            float v = lsum[mt][j];
            v += __shfl_xor_sync(0xffffffffu, v, 1);
            v += __shfl_xor_sync(0xffffffffu, v, 2);
            inv[mt][j] = 1.0f / v;
        }

    // ctx epilogue: fp16 store (identical rounding to former out_mma pack)
    #pragma unroll
    for (int mt = 0; mt < 2; mt++) {
        int r0 = q0 + w * 32 + 16 * mt + (l >> 2);
        #pragma unroll
        for (int nt = 0; nt < 4; nt++) {
            int col = h * HDIM + 8 * nt + 2 * (l & 3);
            *(unsigned*)&g_ctxh[((size_t)b * SEQ + r0) * HID + col] =
                pack_h2(o[mt][nt][0] * inv[mt][0], o[mt][nt][1] * inv[mt][0]);
            *(unsigned*)&g_ctxh[((size_t)b * SEQ + r0 + 8) * HID + col] =
                pack_h2(o[mt][nt][2] * inv[mt][1], o[mt][nt][3] * inv[mt][1]);
        }
    }
}

// ---------------------------------------------------------------------------
extern "C" void kernel_launch(void* const* d_in, const int* in_sizes, int n_in,
                              void* d_out, int out_size) {
    const float* x     = (const float*)d_in[0];
    const float* w_qkv = (const float*)d_in[1];
    const float* b_qkv = (const float*)d_in[2];
    const float* w_out = (const float*)d_in[3];
    const float* b_out = (const float*)d_in[4];
    float* out = (float*)d_out;

    prep_half<<<(NPREP + 255) / 256, 256>>>(x, w_qkv, w_out);
    qkv_mma<<<dim3(6, ROWS / 128), 256>>>(b_qkv);
    attn_mma<<<dim3(SEQ / 256, BATCH * NHEADS), 256>>>();
    out_mma<<<dim3(2, ROWS / 128), 256>>>(b_out, out);
}